// round 1
// baseline (speedup 1.0000x reference)
#include <cuda_runtime.h>
#include <math.h>

#define NA     4096
#define NWORDS 16384
#define DIM    128
#define NZCAP  256
#define CK     23

// ------------------------- scratch (no allocations allowed) -------------------------
__device__ float g_xs[NA * DIM];
__device__ float g_hs[NA * DIM];
__device__ int   g_nzidx[NA * NZCAP];
__device__ int   g_nzcnt[NA];
__device__ float g_imgA[NWORDS * DIM];
__device__ float g_imgB[NWORDS * DIM];
__device__ float g_hsatt[NWORDS * DIM];
__device__ float g_part[128 * DIM];
__device__ float g_compound[DIM];
__device__ float g_hatt[DIM];
__device__ float g_protein[DIM];

// ------------------------- embedding gather -------------------------
__global__ void gather_kernel(const int* __restrict__ idx, const float* __restrict__ emb,
                              float* __restrict__ out, int n) {
    int i = blockIdx.x * blockDim.x + threadIdx.x;
    if (i < n * DIM) {
        int row = i >> 7;
        int c   = i & 127;
        out[i] = emb[(size_t)idx[row] * DIM + c];
    }
}

// ------------------------- sparse adjacency build (deterministic, ordered) -------------------------
__global__ void build_nz(const float* __restrict__ adj) {
    int warp = (blockIdx.x * blockDim.x + threadIdx.x) >> 5;
    int lane = threadIdx.x & 31;
    if (warp >= NA) return;
    const float* row = adj + (size_t)warp * NA;
    int base = 0;
    for (int j0 = 0; j0 < NA; j0 += 32) {
        float v = row[j0 + lane];
        unsigned mask = __ballot_sync(0xffffffffu, v != 0.f);
        if (v != 0.f) {
            int r = __popc(mask & ((1u << lane) - 1));
            int p = base + r;
            if (p < NZCAP) g_nzidx[warp * NZCAP + p] = j0 + lane;
        }
        base += __popc(mask);
    }
    if (lane == 0) g_nzcnt[warp] = base < NZCAP ? base : NZCAP;
}

// ------------------------- Y = relu(X @ W^T + b), N=K=128 -------------------------
// block: 256 threads, 32 rows per block. W in smem padded to 129 (conflict-free),
// X rows broadcast. 4x4 micro-tile per thread.
__global__ void __launch_bounds__(256) linear_relu(const float* __restrict__ X,
                                                   const float* __restrict__ W,
                                                   const float* __restrict__ b,
                                                   float* __restrict__ Y) {
    extern __shared__ float sm[];
    float* sW = sm;                 // [128][129]
    float* sX = sm + 128 * 129;     // [32][128]
    int tid = threadIdx.x;
    for (int idx = tid; idx < 128 * 128; idx += 256) {
        int j = idx >> 7, k = idx & 127;
        sW[j * 129 + k] = W[idx];
    }
    int r0 = blockIdx.x * 32;
    for (int idx = tid; idx < 32 * 128; idx += 256)
        sX[idx] = X[(size_t)r0 * 128 + idx];
    __syncthreads();

    int lane = tid & 31;
    int rg   = tid >> 5;        // 0..7, warp-uniform -> sX loads broadcast
    int i0   = rg * 4;
    float acc[4][4];
#pragma unroll
    for (int r = 0; r < 4; ++r)
#pragma unroll
        for (int q = 0; q < 4; ++q) acc[r][q] = 0.f;

#pragma unroll 4
    for (int k = 0; k < 128; ++k) {
        float a0 = sX[(i0 + 0) * 128 + k];
        float a1 = sX[(i0 + 1) * 128 + k];
        float a2 = sX[(i0 + 2) * 128 + k];
        float a3 = sX[(i0 + 3) * 128 + k];
#pragma unroll
        for (int q = 0; q < 4; ++q) {
            float w = sW[(lane + q * 32) * 129 + k];
            acc[0][q] += a0 * w;
            acc[1][q] += a1 * w;
            acc[2][q] += a2 * w;
            acc[3][q] += a3 * w;
        }
    }
#pragma unroll
    for (int r = 0; r < 4; ++r) {
        int row = r0 + i0 + r;
#pragma unroll
        for (int q = 0; q < 4; ++q) {
            int j = lane + q * 32;
            float v = acc[r][q] + b[j];
            Y[(size_t)row * 128 + j] = v > 0.f ? v : 0.f;
        }
    }
}

// ------------------------- xs += A_sparse @ hs -------------------------
__global__ void spmm_add(const float* __restrict__ hs) {
    int row = blockIdx.x;
    int c   = threadIdx.x;   // 128 threads
    int cnt = g_nzcnt[row];
    const int* nz = g_nzidx + row * NZCAP;
    float acc = 0.f;
    int t = 0;
    for (; t + 4 <= cnt; t += 4) {
        int j0 = nz[t], j1 = nz[t + 1], j2 = nz[t + 2], j3 = nz[t + 3];
        acc += hs[(size_t)j0 * DIM + c];
        acc += hs[(size_t)j1 * DIM + c];
        acc += hs[(size_t)j2 * DIM + c];
        acc += hs[(size_t)j3 * DIM + c];
    }
    for (; t < cnt; ++t) acc += hs[(size_t)nz[t] * DIM + c];
    g_xs[row * DIM + c] += acc;
}

// ------------------------- deterministic column-sum reductions -------------------------
__global__ void colsum_partial(const float* __restrict__ X, float* __restrict__ part,
                               int rows_per_block) {
    int c = threadIdx.x;
    int r0 = blockIdx.x * rows_per_block;
    float acc = 0.f;
    for (int r = 0; r < rows_per_block; ++r) acc += X[(size_t)(r0 + r) * DIM + c];
    part[blockIdx.x * DIM + c] = acc;
}

__global__ void colsum_combine(const float* __restrict__ part, int nparts, float scale,
                               float* __restrict__ out) {
    int c = threadIdx.x;
    float acc = 0.f;
    for (int b = 0; b < nparts; ++b) acc += part[b * DIM + c];
    out[c] = acc * scale;
}

// ------------------------- 23x23 SAME conv + bias + leaky_relu -------------------------
// block (128,4): 32 output rows x 128 cols; thread -> 1 col, 8 output rows.
// smem input tile 54 x 150 (padded to 152). Sliding-row structure:
// per dc: 30 input LDS + 23 weight LDS -> 184 FMAs (constant-index unroll).
__global__ void __launch_bounds__(512, 2) conv_leaky(const float* __restrict__ in,
                                                     float* __restrict__ out,
                                                     const float* __restrict__ kw,
                                                     const float* __restrict__ kb) {
    __shared__ float s_in[54 * 152];
    __shared__ float s_k[CK * CK];
    int tid = threadIdx.x + threadIdx.y * 128;
    int r0  = blockIdx.x * 32;

    for (int idx = tid; idx < 54 * 150; idx += 512) {
        int rr = idx / 150;
        int cc = idx - rr * 150;
        int gr = r0 - 11 + rr;
        int gc = cc - 11;
        float v = 0.f;
        if (gr >= 0 && gr < NWORDS && gc >= 0 && gc < DIM)
            v = in[(size_t)gr * DIM + gc];
        s_in[rr * 152 + cc] = v;
    }
    for (int idx = tid; idx < CK * CK; idx += 512) s_k[idx] = kw[idx];
    __syncthreads();

    float bias = kb[0];
    int c     = threadIdx.x;
    int rbase = threadIdx.y * 8;
    float acc[8];
#pragma unroll
    for (int o = 0; o < 8; ++o) acc[o] = 0.f;

    for (int dc = 0; dc < CK; ++dc) {
        float wc[CK];
#pragma unroll
        for (int dr = 0; dr < CK; ++dr) wc[dr] = s_k[dr * CK + dc];
        const float* col = s_in + rbase * 152 + c + dc;
#pragma unroll
        for (int R = 0; R < 30; ++R) {
            float v = col[R * 152];
#pragma unroll
            for (int dr = 0; dr < CK; ++dr) {
                int o = R - dr;
                if (o >= 0 && o < 8) acc[o] += v * wc[dr];
            }
        }
    }
#pragma unroll
    for (int o = 0; o < 8; ++o) {
        float v = acc[o] + bias;
        out[(size_t)(r0 + rbase + o) * DIM + c] = v > 0.f ? v : 0.01f * v;
    }
}

// ------------------------- h = relu(compound @ W_att^T + b) (single row) -------------------------
__global__ void small_linear_relu(const float* __restrict__ xin, const float* __restrict__ W,
                                  const float* __restrict__ b, float* __restrict__ out) {
    __shared__ float sx[DIM];
    int j = threadIdx.x;
    sx[j] = xin[j];
    __syncthreads();
    float acc = b[j];
    for (int k = 0; k < DIM; ++k) acc += sx[k] * W[j * DIM + k];
    out[j] = acc > 0.f ? acc : 0.f;
}

// ------------------------- protein = mean_m tanh(h . hs_m) * hs_m  (partials) -------------------------
__global__ void protein_partial(const float* __restrict__ hs) {
    __shared__ float sh[DIM];
    __shared__ float sacc[4][DIM];
    int tid  = threadIdx.x;      // 128
    int lane = tid & 31;
    int w    = tid >> 5;
    sh[tid] = g_hatt[tid];
    __syncthreads();
    float h0 = sh[lane], h1 = sh[lane + 32], h2 = sh[lane + 64], h3 = sh[lane + 96];
    float a0 = 0.f, a1 = 0.f, a2 = 0.f, a3 = 0.f;
    int m0 = blockIdx.x * 128 + w * 32;
    for (int mi = 0; mi < 32; ++mi) {
        const float* row = hs + (size_t)(m0 + mi) * DIM;
        float d = row[lane] * h0 + row[lane + 32] * h1 + row[lane + 64] * h2 + row[lane + 96] * h3;
#pragma unroll
        for (int off = 16; off; off >>= 1) d += __shfl_xor_sync(0xffffffffu, d, off);
        float t = tanhf(d);
        float4 v = *reinterpret_cast<const float4*>(row + lane * 4);
        a0 += t * v.x;
        a1 += t * v.y;
        a2 += t * v.z;
        a3 += t * v.w;
    }
    sacc[w][lane * 4 + 0] = a0;
    sacc[w][lane * 4 + 1] = a1;
    sacc[w][lane * 4 + 2] = a2;
    sacc[w][lane * 4 + 3] = a3;
    __syncthreads();
    g_part[blockIdx.x * DIM + tid] =
        sacc[0][tid] + sacc[1][tid] + sacc[2][tid] + sacc[3][tid];
}

// ------------------------- final 2-layer MLP + scalar head -------------------------
__global__ void final_mlp(const float* __restrict__ Wout, const float* __restrict__ bout,
                          const float* __restrict__ Wint, const float* __restrict__ bint,
                          float* __restrict__ out) {
    __shared__ float cat[256];
    __shared__ float red[256];
    int t = threadIdx.x;   // 256
    if (t < 128) {
        cat[t]       = g_compound[t];
        cat[t + 128] = g_protein[t];
    }
    __syncthreads();
    for (int l = 0; l < 2; ++l) {
        const float* Wl = Wout + l * 256 * 256;
        float acc = bout[l * 256 + t];
        for (int k = 0; k < 256; ++k) acc += cat[k] * Wl[t * 256 + k];
        __syncthreads();
        cat[t] = acc > 0.f ? acc : 0.f;
        __syncthreads();
    }
    red[t] = cat[t] * Wint[t];
    __syncthreads();
    for (int s = 128; s; s >>= 1) {
        if (t < s) red[t] += red[t + s];
        __syncthreads();
    }
    if (t == 0) out[0] = red[0] + bint[0];
}

// ------------------------- launch -------------------------
extern "C" void kernel_launch(void* const* d_in, const int* in_sizes, int n_in,
                              void* d_out, int out_size) {
    const int*   fingerprints = (const int*)d_in[0];
    const float* adjacency    = (const float*)d_in[1];
    const int*   words        = (const int*)d_in[2];
    const float* emb_fp       = (const float*)d_in[3];
    const float* emb_word     = (const float*)d_in[4];
    const float* W_gnn_w      = (const float*)d_in[5];
    const float* W_gnn_b      = (const float*)d_in[6];
    const float* conv_w       = (const float*)d_in[7];
    const float* conv_b       = (const float*)d_in[8];
    const float* W_att_w      = (const float*)d_in[9];
    const float* W_att_b      = (const float*)d_in[10];
    const float* W_out_w      = (const float*)d_in[11];
    const float* W_out_b      = (const float*)d_in[12];
    const float* W_int_w      = (const float*)d_in[13];
    const float* W_int_b      = (const float*)d_in[14];
    float* out = (float*)d_out;

    float *xs, *hs, *imgA, *imgB, *hsatt, *part, *comp, *hatt, *prot;
    cudaGetSymbolAddress((void**)&xs,    g_xs);
    cudaGetSymbolAddress((void**)&hs,    g_hs);
    cudaGetSymbolAddress((void**)&imgA,  g_imgA);
    cudaGetSymbolAddress((void**)&imgB,  g_imgB);
    cudaGetSymbolAddress((void**)&hsatt, g_hsatt);
    cudaGetSymbolAddress((void**)&part,  g_part);
    cudaGetSymbolAddress((void**)&comp,  g_compound);
    cudaGetSymbolAddress((void**)&hatt,  g_hatt);
    cudaGetSymbolAddress((void**)&prot,  g_protein);

    int smem_lin = (128 * 129 + 32 * 128) * (int)sizeof(float);
    cudaFuncSetAttribute(linear_relu, cudaFuncAttributeMaxDynamicSharedMemorySize, smem_lin);

    // ---- compound (GNN) ----
    gather_kernel<<<(NA * DIM + 255) / 256, 256>>>(fingerprints, emb_fp, xs, NA);
    build_nz<<<NA / 8, 256>>>(adjacency);
    for (int l = 0; l < 3; ++l) {
        linear_relu<<<NA / 32, 256, smem_lin>>>(xs, W_gnn_w + l * DIM * DIM,
                                                W_gnn_b + l * DIM, hs);
        spmm_add<<<NA, 128>>>(hs);
    }
    colsum_partial<<<32, 128>>>(xs, part, NA / 32);
    colsum_combine<<<1, 128>>>(part, 32, 1.0f / NA, comp);

    // ---- protein (CNN + attention) ----
    gather_kernel<<<(NWORDS * DIM + 255) / 256, 256>>>(words, emb_word, imgA, NWORDS);
    conv_leaky<<<NWORDS / 32, dim3(128, 4)>>>(imgA, imgB, conv_w + 0 * CK * CK, conv_b + 0);
    conv_leaky<<<NWORDS / 32, dim3(128, 4)>>>(imgB, imgA, conv_w + 1 * CK * CK, conv_b + 1);
    conv_leaky<<<NWORDS / 32, dim3(128, 4)>>>(imgA, imgB, conv_w + 2 * CK * CK, conv_b + 2);
    linear_relu<<<NWORDS / 32, 256, smem_lin>>>(imgB, W_att_w, W_att_b, hsatt);
    small_linear_relu<<<1, 128>>>(comp, W_att_w, W_att_b, hatt);
    protein_partial<<<NWORDS / 128, 128>>>(hsatt);
    colsum_combine<<<1, 128>>>(part, 128, 1.0f / NWORDS, prot);

    // ---- head ----
    final_mlp<<<1, 256>>>(W_out_w, W_out_b, W_int_w, W_int_b, out);
}

// round 2
// speedup vs baseline: 1.0547x; 1.0547x over previous
#include <cuda_runtime.h>
#include <math.h>

#define NA     4096
#define NWORDS 16384
#define DIM    128
#define NZCAP  256
#define CK     23

// ------------------------- scratch (no allocations allowed) -------------------------
__device__ float g_xs[NA * DIM];
__device__ float g_hs[NA * DIM];
__device__ int   g_nzidx[NA * NZCAP];
__device__ int   g_nzcnt[NA];
__device__ float g_imgA[NWORDS * DIM];
__device__ float g_imgB[NWORDS * DIM];
__device__ float g_hsatt[NWORDS * DIM];
__device__ float g_part[128 * DIM];
__device__ float g_compound[DIM];
__device__ float g_hatt[DIM];
__device__ float g_protein[DIM];

// ------------------------- f32x2 helpers -------------------------
__device__ __forceinline__ void ffma2(unsigned long long& d, unsigned long long a,
                                      unsigned long long b) {
    asm("fma.rn.f32x2 %0, %1, %2, %0;" : "+l"(d) : "l"(a), "l"(b));
}
__device__ __forceinline__ float lo32(unsigned long long v) {
    return __uint_as_float((unsigned)(v & 0xffffffffull));
}
__device__ __forceinline__ float hi32(unsigned long long v) {
    return __uint_as_float((unsigned)(v >> 32));
}

// ------------------------- embedding gather -------------------------
__global__ void gather_kernel(const int* __restrict__ idx, const float* __restrict__ emb,
                              float* __restrict__ out, int n) {
    int i = blockIdx.x * blockDim.x + threadIdx.x;
    if (i < n * DIM) {
        int row = i >> 7;
        int c   = i & 127;
        out[i] = emb[(size_t)idx[row] * DIM + c];
    }
}

// ------------------------- sparse adjacency build (deterministic, ordered) -------------------------
__global__ void build_nz(const float* __restrict__ adj) {
    int warp = (blockIdx.x * blockDim.x + threadIdx.x) >> 5;
    int lane = threadIdx.x & 31;
    if (warp >= NA) return;
    const float* row = adj + (size_t)warp * NA;
    int base = 0;
    for (int j0 = 0; j0 < NA; j0 += 32) {
        float v = row[j0 + lane];
        unsigned mask = __ballot_sync(0xffffffffu, v != 0.f);
        if (v != 0.f) {
            int r = __popc(mask & ((1u << lane) - 1));
            int p = base + r;
            if (p < NZCAP) g_nzidx[warp * NZCAP + p] = j0 + lane;
        }
        base += __popc(mask);
    }
    if (lane == 0) g_nzcnt[warp] = base < NZCAP ? base : NZCAP;
}

// ------------------------- Y = relu(X @ W^T + b), N=K=128 -------------------------
__global__ void __launch_bounds__(256) linear_relu(const float* __restrict__ X,
                                                   const float* __restrict__ W,
                                                   const float* __restrict__ b,
                                                   float* __restrict__ Y) {
    extern __shared__ float sm[];
    float* sW = sm;                 // [128][129]
    float* sX = sm + 128 * 129;     // [32][128]
    int tid = threadIdx.x;
    for (int idx = tid; idx < 128 * 128; idx += 256) {
        int j = idx >> 7, k = idx & 127;
        sW[j * 129 + k] = W[idx];
    }
    int r0 = blockIdx.x * 32;
    for (int idx = tid; idx < 32 * 128; idx += 256)
        sX[idx] = X[(size_t)r0 * 128 + idx];
    __syncthreads();

    int lane = tid & 31;
    int rg   = tid >> 5;
    int i0   = rg * 4;
    float acc[4][4];
#pragma unroll
    for (int r = 0; r < 4; ++r)
#pragma unroll
        for (int q = 0; q < 4; ++q) acc[r][q] = 0.f;

#pragma unroll 4
    for (int k = 0; k < 128; ++k) {
        float a0 = sX[(i0 + 0) * 128 + k];
        float a1 = sX[(i0 + 1) * 128 + k];
        float a2 = sX[(i0 + 2) * 128 + k];
        float a3 = sX[(i0 + 3) * 128 + k];
#pragma unroll
        for (int q = 0; q < 4; ++q) {
            float w = sW[(lane + q * 32) * 129 + k];
            acc[0][q] += a0 * w;
            acc[1][q] += a1 * w;
            acc[2][q] += a2 * w;
            acc[3][q] += a3 * w;
        }
    }
#pragma unroll
    for (int r = 0; r < 4; ++r) {
        int row = r0 + i0 + r;
#pragma unroll
        for (int q = 0; q < 4; ++q) {
            int j = lane + q * 32;
            float v = acc[r][q] + b[j];
            Y[(size_t)row * 128 + j] = v > 0.f ? v : 0.f;
        }
    }
}

// ------------------------- xs += A_sparse @ hs (4-way MLP split) -------------------------
__global__ void spmm_add(const float* __restrict__ hs) {
    __shared__ float sacc[4][128];
    int row = blockIdx.x;
    int c   = threadIdx.x;   // 128
    int yy  = threadIdx.y;   // 4
    int cnt = g_nzcnt[row];
    const int* nz = g_nzidx + row * NZCAP;
    float acc = 0.f;
    for (int t = yy; t < cnt; t += 4)
        acc += hs[(size_t)nz[t] * DIM + c];
    sacc[yy][c] = acc;
    __syncthreads();
    if (yy == 0)
        g_xs[row * DIM + c] += (sacc[0][c] + sacc[1][c]) + (sacc[2][c] + sacc[3][c]);
}

// ------------------------- deterministic column-sum reductions -------------------------
__global__ void colsum_partial(const float* __restrict__ X, float* __restrict__ part,
                               int rows_per_block) {
    int c = threadIdx.x;
    int r0 = blockIdx.x * rows_per_block;
    float acc = 0.f;
    for (int r = 0; r < rows_per_block; ++r) acc += X[(size_t)(r0 + r) * DIM + c];
    part[blockIdx.x * DIM + c] = acc;
}

__global__ void colsum_combine(const float* __restrict__ part, int nparts, float scale,
                               float* __restrict__ out) {
    int c = threadIdx.x;
    float acc = 0.f;
    for (int b = 0; b < nparts; ++b) acc += part[b * DIM + c];
    out[c] = acc * scale;
}

// ------------------------- 23x23 SAME conv + bias + leaky_relu, packed f32x2 -------------------------
// block (64,4): 64 column-pairs (c, c+64) x 4 row-groups x 8 rows = 32 out rows x 128 cols.
// smem holds input as float2 pairs: pair qi covers cols (qi-11, qi+53); 54 rows x 88 pitch.
// weights pre-duplicated as (w,w) float2. Inner loop: 1 LDS.64 -> up to 8 FFMA2.
#define SPITCH 88
__global__ void __launch_bounds__(256) conv_leaky(const float* __restrict__ in,
                                                  float* __restrict__ out,
                                                  const float* __restrict__ kw,
                                                  const float* __restrict__ kb) {
    __shared__ float2 s_in2[54 * SPITCH];
    __shared__ float2 s_k2[CK * CK];
    int tid = threadIdx.x + threadIdx.y * 64;
    int r0  = blockIdx.x * 32;

    // input tile: rows r0-11 .. r0+42, column-pairs qi=0..85 -> (qi-11, qi+53)
    for (int idx = tid; idx < 54 * 86; idx += 256) {
        int rr = idx / 86;
        int qi = idx - rr * 86;
        int gr = r0 - 11 + rr;
        int q  = qi - 11;
        float lo = 0.f, hi = 0.f;
        if (gr >= 0 && gr < NWORDS) {
            const float* grow = in + (size_t)gr * DIM;
            if (q >= 0)       lo = grow[q];        // q <= 74 < 128 always
            if (q + 64 < 128) hi = grow[q + 64];   // q+64 >= 53 >= 0 always
        }
        s_in2[rr * SPITCH + qi] = make_float2(lo, hi);
    }
    for (int idx = tid; idx < CK * CK; idx += 256) {
        float w = kw[idx];
        s_k2[idx] = make_float2(w, w);
    }
    __syncthreads();

    float bias = kb[0];
    int cp    = threadIdx.x;       // column pair
    int rbase = threadIdx.y * 8;

    unsigned long long acc2[8];
#pragma unroll
    for (int o = 0; o < 8; ++o) acc2[o] = 0ull;

#pragma unroll 1
    for (int dc = 0; dc < CK; ++dc) {
        unsigned long long wc2[CK];
#pragma unroll
        for (int dr = 0; dr < CK; ++dr)
            wc2[dr] = *reinterpret_cast<const unsigned long long*>(&s_k2[dr * CK + dc]);

        const unsigned long long* col =
            reinterpret_cast<const unsigned long long*>(s_in2) + rbase * SPITCH + cp + dc;
#pragma unroll
        for (int R = 0; R < 30; ++R) {
            unsigned long long v2 = col[R * SPITCH];
#pragma unroll
            for (int dr = 0; dr < CK; ++dr) {
                int o = R - dr;
                if (o >= 0 && o < 8) ffma2(acc2[o], v2, wc2[dr]);
            }
        }
    }

#pragma unroll
    for (int o = 0; o < 8; ++o) {
        int row = r0 + rbase + o;
        float vl = lo32(acc2[o]) + bias;
        float vh = hi32(acc2[o]) + bias;
        out[(size_t)row * DIM + cp]      = vl > 0.f ? vl : 0.01f * vl;
        out[(size_t)row * DIM + cp + 64] = vh > 0.f ? vh : 0.01f * vh;
    }
}

// ------------------------- h = relu(compound @ W_att^T + b) (single row) -------------------------
__global__ void small_linear_relu(const float* __restrict__ xin, const float* __restrict__ W,
                                  const float* __restrict__ b, float* __restrict__ out) {
    __shared__ float sx[DIM];
    int j = threadIdx.x;
    sx[j] = xin[j];
    __syncthreads();
    float acc = b[j];
    for (int k = 0; k < DIM; ++k) acc += sx[k] * W[j * DIM + k];
    out[j] = acc > 0.f ? acc : 0.f;
}

// ------------------------- protein = mean_m tanh(h . hs_m) * hs_m  (partials) -------------------------
__global__ void protein_partial(const float* __restrict__ hs) {
    __shared__ float sh[DIM];
    __shared__ float sacc[4][DIM];
    int tid  = threadIdx.x;      // 128
    int lane = tid & 31;
    int w    = tid >> 5;
    sh[tid] = g_hatt[tid];
    __syncthreads();
    float h0 = sh[lane], h1 = sh[lane + 32], h2 = sh[lane + 64], h3 = sh[lane + 96];
    float a0 = 0.f, a1 = 0.f, a2 = 0.f, a3 = 0.f;
    int m0 = blockIdx.x * 128 + w * 32;
    for (int mi = 0; mi < 32; ++mi) {
        const float* row = hs + (size_t)(m0 + mi) * DIM;
        float d = row[lane] * h0 + row[lane + 32] * h1 + row[lane + 64] * h2 + row[lane + 96] * h3;
#pragma unroll
        for (int off = 16; off; off >>= 1) d += __shfl_xor_sync(0xffffffffu, d, off);
        float t = tanhf(d);
        float4 v = *reinterpret_cast<const float4*>(row + lane * 4);
        a0 += t * v.x;
        a1 += t * v.y;
        a2 += t * v.z;
        a3 += t * v.w;
    }
    sacc[w][lane * 4 + 0] = a0;
    sacc[w][lane * 4 + 1] = a1;
    sacc[w][lane * 4 + 2] = a2;
    sacc[w][lane * 4 + 3] = a3;
    __syncthreads();
    g_part[blockIdx.x * DIM + tid] =
        sacc[0][tid] + sacc[1][tid] + sacc[2][tid] + sacc[3][tid];
}

// ------------------------- final 2-layer MLP + scalar head -------------------------
__global__ void final_mlp(const float* __restrict__ Wout, const float* __restrict__ bout,
                          const float* __restrict__ Wint, const float* __restrict__ bint,
                          float* __restrict__ out) {
    __shared__ float cat[256];
    __shared__ float red[256];
    int t = threadIdx.x;   // 256
    if (t < 128) {
        cat[t]       = g_compound[t];
        cat[t + 128] = g_protein[t];
    }
    __syncthreads();
    for (int l = 0; l < 2; ++l) {
        const float* Wl = Wout + l * 256 * 256;
        float acc = bout[l * 256 + t];
        for (int k = 0; k < 256; ++k) acc += cat[k] * Wl[t * 256 + k];
        __syncthreads();
        cat[t] = acc > 0.f ? acc : 0.f;
        __syncthreads();
    }
    red[t] = cat[t] * Wint[t];
    __syncthreads();
    for (int s = 128; s; s >>= 1) {
        if (t < s) red[t] += red[t + s];
        __syncthreads();
    }
    if (t == 0) out[0] = red[0] + bint[0];
}

// ------------------------- launch -------------------------
extern "C" void kernel_launch(void* const* d_in, const int* in_sizes, int n_in,
                              void* d_out, int out_size) {
    const int*   fingerprints = (const int*)d_in[0];
    const float* adjacency    = (const float*)d_in[1];
    const int*   words        = (const int*)d_in[2];
    const float* emb_fp       = (const float*)d_in[3];
    const float* emb_word     = (const float*)d_in[4];
    const float* W_gnn_w      = (const float*)d_in[5];
    const float* W_gnn_b      = (const float*)d_in[6];
    const float* conv_w       = (const float*)d_in[7];
    const float* conv_b       = (const float*)d_in[8];
    const float* W_att_w      = (const float*)d_in[9];
    const float* W_att_b      = (const float*)d_in[10];
    const float* W_out_w      = (const float*)d_in[11];
    const float* W_out_b      = (const float*)d_in[12];
    const float* W_int_w      = (const float*)d_in[13];
    const float* W_int_b      = (const float*)d_in[14];
    float* out = (float*)d_out;

    float *xs, *hs, *imgA, *imgB, *hsatt, *part, *comp, *hatt, *prot;
    cudaGetSymbolAddress((void**)&xs,    g_xs);
    cudaGetSymbolAddress((void**)&hs,    g_hs);
    cudaGetSymbolAddress((void**)&imgA,  g_imgA);
    cudaGetSymbolAddress((void**)&imgB,  g_imgB);
    cudaGetSymbolAddress((void**)&hsatt, g_hsatt);
    cudaGetSymbolAddress((void**)&part,  g_part);
    cudaGetSymbolAddress((void**)&comp,  g_compound);
    cudaGetSymbolAddress((void**)&hatt,  g_hatt);
    cudaGetSymbolAddress((void**)&prot,  g_protein);

    int smem_lin = (128 * 129 + 32 * 128) * (int)sizeof(float);
    cudaFuncSetAttribute(linear_relu, cudaFuncAttributeMaxDynamicSharedMemorySize, smem_lin);

    // ---- compound (GNN) ----
    gather_kernel<<<(NA * DIM + 255) / 256, 256>>>(fingerprints, emb_fp, xs, NA);
    build_nz<<<NA / 8, 256>>>(adjacency);
    for (int l = 0; l < 3; ++l) {
        linear_relu<<<NA / 32, 256, smem_lin>>>(xs, W_gnn_w + l * DIM * DIM,
                                                W_gnn_b + l * DIM, hs);
        spmm_add<<<NA, dim3(128, 4)>>>(hs);
    }
    colsum_partial<<<32, 128>>>(xs, part, NA / 32);
    colsum_combine<<<1, 128>>>(part, 32, 1.0f / NA, comp);

    // ---- protein (CNN + attention) ----
    gather_kernel<<<(NWORDS * DIM + 255) / 256, 256>>>(words, emb_word, imgA, NWORDS);
    conv_leaky<<<NWORDS / 32, dim3(64, 4)>>>(imgA, imgB, conv_w + 0 * CK * CK, conv_b + 0);
    conv_leaky<<<NWORDS / 32, dim3(64, 4)>>>(imgB, imgA, conv_w + 1 * CK * CK, conv_b + 1);
    conv_leaky<<<NWORDS / 32, dim3(64, 4)>>>(imgA, imgB, conv_w + 2 * CK * CK, conv_b + 2);
    linear_relu<<<NWORDS / 32, 256, smem_lin>>>(imgB, W_att_w, W_att_b, hsatt);
    small_linear_relu<<<1, 128>>>(comp, W_att_w, W_att_b, hatt);
    protein_partial<<<NWORDS / 128, 128>>>(hsatt);
    colsum_combine<<<1, 128>>>(part, 128, 1.0f / NWORDS, prot);

    // ---- head ----
    final_mlp<<<1, 256>>>(W_out_w, W_out_b, W_int_w, W_int_b, out);
}

// round 3
// speedup vs baseline: 1.0992x; 1.0422x over previous
#include <cuda_runtime.h>
#include <math.h>

#define NA     4096
#define NWORDS 16384
#define DIM    128
#define NZCAP  256
#define CK     23

// ------------------------- scratch (no allocations allowed) -------------------------
__device__ float g_xs[NA * DIM];
__device__ float g_hs[NA * DIM];
__device__ int   g_nzidx[NA * NZCAP];
__device__ int   g_nzcnt[NA];
__device__ float g_imgA[NWORDS * DIM];
__device__ float g_imgB[NWORDS * DIM];
__device__ float g_hsatt[NWORDS * DIM];
__device__ float g_part[128 * DIM];
__device__ float g_compound[DIM];
__device__ float g_hatt[DIM];
__device__ float g_protein[DIM];

// ------------------------- f32x2 helpers -------------------------
__device__ __forceinline__ void ffma2(unsigned long long& d, unsigned long long a,
                                      unsigned long long b) {
    asm("fma.rn.f32x2 %0, %1, %2, %0;" : "+l"(d) : "l"(a), "l"(b));
}
__device__ __forceinline__ float lo32(unsigned long long v) {
    return __uint_as_float((unsigned)(v & 0xffffffffull));
}
__device__ __forceinline__ float hi32(unsigned long long v) {
    return __uint_as_float((unsigned)(v >> 32));
}

// ------------------------- embedding gather -------------------------
__global__ void gather_kernel(const int* __restrict__ idx, const float* __restrict__ emb,
                              float* __restrict__ out, int n) {
    int i = blockIdx.x * blockDim.x + threadIdx.x;
    if (i < n * DIM) {
        int row = i >> 7;
        int c   = i & 127;
        out[i] = emb[(size_t)idx[row] * DIM + c];
    }
}

// ------------------------- sparse adjacency build (deterministic, ordered) -------------------------
__global__ void build_nz(const float* __restrict__ adj) {
    int warp = (blockIdx.x * blockDim.x + threadIdx.x) >> 5;
    int lane = threadIdx.x & 31;
    if (warp >= NA) return;
    const float* row = adj + (size_t)warp * NA;
    int base = 0;
    for (int j0 = 0; j0 < NA; j0 += 32) {
        float v = row[j0 + lane];
        unsigned mask = __ballot_sync(0xffffffffu, v != 0.f);
        if (v != 0.f) {
            int r = __popc(mask & ((1u << lane) - 1));
            int p = base + r;
            if (p < NZCAP) g_nzidx[warp * NZCAP + p] = j0 + lane;
        }
        base += __popc(mask);
    }
    if (lane == 0) g_nzcnt[warp] = base < NZCAP ? base : NZCAP;
}

// ------------------------- Y = relu(X @ W^T + b), N=K=128 -------------------------
__global__ void __launch_bounds__(256) linear_relu(const float* __restrict__ X,
                                                   const float* __restrict__ W,
                                                   const float* __restrict__ b,
                                                   float* __restrict__ Y) {
    extern __shared__ float sm[];
    float* sW = sm;                 // [128][129]
    float* sX = sm + 128 * 129;     // [32][128]
    int tid = threadIdx.x;
    for (int idx = tid; idx < 128 * 128; idx += 256) {
        int j = idx >> 7, k = idx & 127;
        sW[j * 129 + k] = W[idx];
    }
    int r0 = blockIdx.x * 32;
    for (int idx = tid; idx < 32 * 128; idx += 256)
        sX[idx] = X[(size_t)r0 * 128 + idx];
    __syncthreads();

    int lane = tid & 31;
    int rg   = tid >> 5;
    int i0   = rg * 4;
    float acc[4][4];
#pragma unroll
    for (int r = 0; r < 4; ++r)
#pragma unroll
        for (int q = 0; q < 4; ++q) acc[r][q] = 0.f;

#pragma unroll 4
    for (int k = 0; k < 128; ++k) {
        float a0 = sX[(i0 + 0) * 128 + k];
        float a1 = sX[(i0 + 1) * 128 + k];
        float a2 = sX[(i0 + 2) * 128 + k];
        float a3 = sX[(i0 + 3) * 128 + k];
#pragma unroll
        for (int q = 0; q < 4; ++q) {
            float w = sW[(lane + q * 32) * 129 + k];
            acc[0][q] += a0 * w;
            acc[1][q] += a1 * w;
            acc[2][q] += a2 * w;
            acc[3][q] += a3 * w;
        }
    }
#pragma unroll
    for (int r = 0; r < 4; ++r) {
        int row = r0 + i0 + r;
#pragma unroll
        for (int q = 0; q < 4; ++q) {
            int j = lane + q * 32;
            float v = acc[r][q] + b[j];
            Y[(size_t)row * 128 + j] = v > 0.f ? v : 0.f;
        }
    }
}

// ------------------------- xs += A_sparse @ hs (warp-per-row, float4 lanes) -------------------------
__global__ void __launch_bounds__(256) spmm_add(const float* __restrict__ hs) {
    int row  = blockIdx.x * 8 + (threadIdx.x >> 5);
    int lane = threadIdx.x & 31;
    int cnt = g_nzcnt[row];
    const int* nz = g_nzidx + row * NZCAP;

    float4 a0 = make_float4(0.f, 0.f, 0.f, 0.f);
    float4 a1 = make_float4(0.f, 0.f, 0.f, 0.f);
    int t = 0;
    for (; t + 2 <= cnt; t += 2) {
        int j0 = nz[t], j1 = nz[t + 1];
        float4 v0 = *reinterpret_cast<const float4*>(hs + (size_t)j0 * DIM + lane * 4);
        float4 v1 = *reinterpret_cast<const float4*>(hs + (size_t)j1 * DIM + lane * 4);
        a0.x += v0.x; a0.y += v0.y; a0.z += v0.z; a0.w += v0.w;
        a1.x += v1.x; a1.y += v1.y; a1.z += v1.z; a1.w += v1.w;
    }
    if (t < cnt) {
        int j0 = nz[t];
        float4 v0 = *reinterpret_cast<const float4*>(hs + (size_t)j0 * DIM + lane * 4);
        a0.x += v0.x; a0.y += v0.y; a0.z += v0.z; a0.w += v0.w;
    }
    float4* dst = reinterpret_cast<float4*>(g_xs + (size_t)row * DIM + lane * 4);
    float4 x = *dst;
    x.x += a0.x + a1.x;
    x.y += a0.y + a1.y;
    x.z += a0.z + a1.z;
    x.w += a0.w + a1.w;
    *dst = x;
}

// ------------------------- deterministic column-sum reductions -------------------------
__global__ void colsum_partial(const float* __restrict__ X, float* __restrict__ part,
                               int rows_per_block) {
    int c = threadIdx.x;
    int r0 = blockIdx.x * rows_per_block;
    float acc = 0.f;
    for (int r = 0; r < rows_per_block; ++r) acc += X[(size_t)(r0 + r) * DIM + c];
    part[blockIdx.x * DIM + c] = acc;
}

__global__ void colsum_combine(const float* __restrict__ part, int nparts, float scale,
                               float* __restrict__ out) {
    int c = threadIdx.x;
    float acc = 0.f;
    for (int b = 0; b < nparts; ++b) acc += part[b * DIM + c];
    out[c] = acc * scale;
}

// ------------------------- 23x23 SAME conv + bias + leaky_relu, packed f32x2 -------------------------
#define SPITCH 88
__global__ void __launch_bounds__(256) conv_leaky(const float* __restrict__ in,
                                                  float* __restrict__ out,
                                                  const float* __restrict__ kw,
                                                  const float* __restrict__ kb) {
    __shared__ float2 s_in2[54 * SPITCH];
    __shared__ float2 s_k2[CK * CK];
    int tid = threadIdx.x + threadIdx.y * 64;
    int r0  = blockIdx.x * 32;

    for (int idx = tid; idx < 54 * 86; idx += 256) {
        int rr = idx / 86;
        int qi = idx - rr * 86;
        int gr = r0 - 11 + rr;
        int q  = qi - 11;
        float lo = 0.f, hi = 0.f;
        if (gr >= 0 && gr < NWORDS) {
            const float* grow = in + (size_t)gr * DIM;
            if (q >= 0)       lo = grow[q];
            if (q + 64 < 128) hi = grow[q + 64];
        }
        s_in2[rr * SPITCH + qi] = make_float2(lo, hi);
    }
    for (int idx = tid; idx < CK * CK; idx += 256) {
        float w = kw[idx];
        s_k2[idx] = make_float2(w, w);
    }
    __syncthreads();

    float bias = kb[0];
    int cp    = threadIdx.x;
    int rbase = threadIdx.y * 8;

    unsigned long long acc2[8];
#pragma unroll
    for (int o = 0; o < 8; ++o) acc2[o] = 0ull;

#pragma unroll 1
    for (int dc = 0; dc < CK; ++dc) {
        unsigned long long wc2[CK];
#pragma unroll
        for (int dr = 0; dr < CK; ++dr)
            wc2[dr] = *reinterpret_cast<const unsigned long long*>(&s_k2[dr * CK + dc]);

        const unsigned long long* col =
            reinterpret_cast<const unsigned long long*>(s_in2) + rbase * SPITCH + cp + dc;
#pragma unroll
        for (int R = 0; R < 30; ++R) {
            unsigned long long v2 = col[R * SPITCH];
#pragma unroll
            for (int dr = 0; dr < CK; ++dr) {
                int o = R - dr;
                if (o >= 0 && o < 8) ffma2(acc2[o], v2, wc2[dr]);
            }
        }
    }

#pragma unroll
    for (int o = 0; o < 8; ++o) {
        int row = r0 + rbase + o;
        float vl = lo32(acc2[o]) + bias;
        float vh = hi32(acc2[o]) + bias;
        out[(size_t)row * DIM + cp]      = vl > 0.f ? vl : 0.01f * vl;
        out[(size_t)row * DIM + cp + 64] = vh > 0.f ? vh : 0.01f * vh;
    }
}

// ------------------------- h = relu(compound @ W_att^T + b) (single row) -------------------------
__global__ void small_linear_relu(const float* __restrict__ xin, const float* __restrict__ W,
                                  const float* __restrict__ b, float* __restrict__ out) {
    __shared__ float sx[DIM];
    int j = threadIdx.x;
    sx[j] = xin[j];
    __syncthreads();
    float acc = b[j];
    for (int k = 0; k < DIM; ++k) acc += sx[k] * W[j * DIM + k];
    out[j] = acc > 0.f ? acc : 0.f;
}

// ------------------------- protein = mean_m tanh(h . hs_m) * hs_m  (partials) -------------------------
__global__ void protein_partial(const float* __restrict__ hs) {
    __shared__ float sh[DIM];
    __shared__ float sacc[4][DIM];
    int tid  = threadIdx.x;
    int lane = tid & 31;
    int w    = tid >> 5;
    sh[tid] = g_hatt[tid];
    __syncthreads();
    float h0 = sh[lane], h1 = sh[lane + 32], h2 = sh[lane + 64], h3 = sh[lane + 96];
    float a0 = 0.f, a1 = 0.f, a2 = 0.f, a3 = 0.f;
    int m0 = blockIdx.x * 128 + w * 32;
    for (int mi = 0; mi < 32; ++mi) {
        const float* row = hs + (size_t)(m0 + mi) * DIM;
        float d = row[lane] * h0 + row[lane + 32] * h1 + row[lane + 64] * h2 + row[lane + 96] * h3;
#pragma unroll
        for (int off = 16; off; off >>= 1) d += __shfl_xor_sync(0xffffffffu, d, off);
        float t = tanhf(d);
        float4 v = *reinterpret_cast<const float4*>(row + lane * 4);
        a0 += t * v.x;
        a1 += t * v.y;
        a2 += t * v.z;
        a3 += t * v.w;
    }
    sacc[w][lane * 4 + 0] = a0;
    sacc[w][lane * 4 + 1] = a1;
    sacc[w][lane * 4 + 2] = a2;
    sacc[w][lane * 4 + 3] = a3;
    __syncthreads();
    g_part[blockIdx.x * DIM + tid] =
        sacc[0][tid] + sacc[1][tid] + sacc[2][tid] + sacc[3][tid];
}

// ------------------------- final 2-layer MLP + scalar head -------------------------
__global__ void final_mlp(const float* __restrict__ Wout, const float* __restrict__ bout,
                          const float* __restrict__ Wint, const float* __restrict__ bint,
                          float* __restrict__ out) {
    __shared__ float cat[256];
    __shared__ float red[256];
    int t = threadIdx.x;
    if (t < 128) {
        cat[t]       = g_compound[t];
        cat[t + 128] = g_protein[t];
    }
    __syncthreads();
    for (int l = 0; l < 2; ++l) {
        const float* Wl = Wout + l * 256 * 256;
        float acc = bout[l * 256 + t];
        for (int k = 0; k < 256; ++k) acc += cat[k] * Wl[t * 256 + k];
        __syncthreads();
        cat[t] = acc > 0.f ? acc : 0.f;
        __syncthreads();
    }
    red[t] = cat[t] * Wint[t];
    __syncthreads();
    for (int s = 128; s; s >>= 1) {
        if (t < s) red[t] += red[t + s];
        __syncthreads();
    }
    if (t == 0) out[0] = red[0] + bint[0];
}

// ------------------------- launch -------------------------
extern "C" void kernel_launch(void* const* d_in, const int* in_sizes, int n_in,
                              void* d_out, int out_size) {
    const int*   fingerprints = (const int*)d_in[0];
    const float* adjacency    = (const float*)d_in[1];
    const int*   words        = (const int*)d_in[2];
    const float* emb_fp       = (const float*)d_in[3];
    const float* emb_word     = (const float*)d_in[4];
    const float* W_gnn_w      = (const float*)d_in[5];
    const float* W_gnn_b      = (const float*)d_in[6];
    const float* conv_w       = (const float*)d_in[7];
    const float* conv_b       = (const float*)d_in[8];
    const float* W_att_w      = (const float*)d_in[9];
    const float* W_att_b      = (const float*)d_in[10];
    const float* W_out_w      = (const float*)d_in[11];
    const float* W_out_b      = (const float*)d_in[12];
    const float* W_int_w      = (const float*)d_in[13];
    const float* W_int_b      = (const float*)d_in[14];
    float* out = (float*)d_out;

    float *xs, *hs, *imgA, *imgB, *hsatt, *part, *comp, *hatt, *prot;
    cudaGetSymbolAddress((void**)&xs,    g_xs);
    cudaGetSymbolAddress((void**)&hs,    g_hs);
    cudaGetSymbolAddress((void**)&imgA,  g_imgA);
    cudaGetSymbolAddress((void**)&imgB,  g_imgB);
    cudaGetSymbolAddress((void**)&hsatt, g_hsatt);
    cudaGetSymbolAddress((void**)&part,  g_part);
    cudaGetSymbolAddress((void**)&comp,  g_compound);
    cudaGetSymbolAddress((void**)&hatt,  g_hatt);
    cudaGetSymbolAddress((void**)&prot,  g_protein);

    int smem_lin = (128 * 129 + 32 * 128) * (int)sizeof(float);
    cudaFuncSetAttribute(linear_relu, cudaFuncAttributeMaxDynamicSharedMemorySize, smem_lin);

    // ---- protein branch first (so ncu -s 5 -c 1 lands on conv3 = launch #6) ----
    gather_kernel<<<(NA * DIM + 255) / 256, 256>>>(fingerprints, emb_fp, xs, NA);       // 1
    build_nz<<<NA / 8, 256>>>(adjacency);                                               // 2
    gather_kernel<<<(NWORDS * DIM + 255) / 256, 256>>>(words, emb_word, imgA, NWORDS);  // 3
    conv_leaky<<<NWORDS / 32, dim3(64, 4)>>>(imgA, imgB, conv_w + 0 * CK * CK, conv_b + 0); // 4
    conv_leaky<<<NWORDS / 32, dim3(64, 4)>>>(imgB, imgA, conv_w + 1 * CK * CK, conv_b + 1); // 5
    conv_leaky<<<NWORDS / 32, dim3(64, 4)>>>(imgA, imgB, conv_w + 2 * CK * CK, conv_b + 2); // 6

    // ---- compound (GNN) ----
    for (int l = 0; l < 3; ++l) {
        linear_relu<<<NA / 32, 256, smem_lin>>>(xs, W_gnn_w + l * DIM * DIM,
                                                W_gnn_b + l * DIM, hs);
        spmm_add<<<NA / 8, 256>>>(hs);
    }
    colsum_partial<<<32, 128>>>(xs, part, NA / 32);
    colsum_combine<<<1, 128>>>(part, 32, 1.0f / NA, comp);

    // ---- protein attention ----
    linear_relu<<<NWORDS / 32, 256, smem_lin>>>(imgB, W_att_w, W_att_b, hsatt);
    small_linear_relu<<<1, 128>>>(comp, W_att_w, W_att_b, hatt);
    protein_partial<<<NWORDS / 128, 128>>>(hsatt);
    colsum_combine<<<1, 128>>>(part, 128, 1.0f / NWORDS, prot);

    // ---- head ----
    final_mlp<<<1, 256>>>(W_out_w, W_out_b, W_int_w, W_int_b, out);
}